// round 5
// baseline (speedup 1.0000x reference)
#include <cuda_runtime.h>

// Per-CTA partial sums + completion counter. 16384/8 = 2048 CTAs for this problem.
__device__ float g_block[65536];
__device__ unsigned int g_count = 0;

__device__ __forceinline__ float warp_sum(float v) {
    #pragma unroll
    for (int off = 16; off > 0; off >>= 1)
        v += __shfl_down_sync(0xFFFFFFFFu, v, off);
    return v;
}

// One warp per i, 8 warps per CTA. Each warp computes loss_i (post-relu);
// the CTA sums its 8 losses into g_block[bid]; the last CTA to finish
// reduces all partials into out[0] (fixed order -> deterministic).
__global__ void __launch_bounds__(256)
triplet_fused(const float* __restrict__ feats,
              const float* __restrict__ label,
              const int*   __restrict__ idx1,
              const int*   __restrict__ idx2,
              float* __restrict__ out,
              int B, int D) {
    const int lane = threadIdx.x & 31;
    const int wid  = threadIdx.x >> 5;
    const int i    = blockIdx.x * 8 + wid;

    __shared__ float wloss[8];
    __shared__ bool  isLast;
    float loss = 0.f;

    if (i < B) {
        // _fix_indices replication (all lanes; broadcast loads of same address)
        const int r1 = idx1[i];
        const int r2 = idx2[i];
        int a = (i + 1 + (r1 % (B - 1))) % B;
        int b = (i + 1 + (r2 % (B - 1))) % B;
        if (b == a) b = (i + 1 + ((r2 + 1) % (B - 1))) % B;

        const float4* __restrict__ A  = (const float4*)(feats + (size_t)i * D);
        const float4* __restrict__ T1 = (const float4*)(feats + (size_t)a * D);
        const float4* __restrict__ T2 = (const float4*)(feats + (size_t)b * D);

        const int n4 = D >> 2;   // 512 for D=2048
        float s1 = 0.f, s2 = 0.f;

        if ((n4 & 127) == 0) {
            // Fast path: chunks of 4 j-steps per warp, 12 front-batched float4 loads.
            const int nchunk = n4 >> 7;          // 4 for D=2048
            for (int c = 0; c < nchunk; ++c) {
                const int base = lane + c * 128;
                float4 av[4], v1[4], v2[4];
                #pragma unroll
                for (int u = 0; u < 4; ++u) av[u] = A[base + u * 32];
                #pragma unroll
                for (int u = 0; u < 4; ++u) v1[u] = T1[base + u * 32];
                #pragma unroll
                for (int u = 0; u < 4; ++u) v2[u] = T2[base + u * 32];
                #pragma unroll
                for (int u = 0; u < 4; ++u) {
                    float d;
                    d = av[u].x - v1[u].x; s1 = fmaf(d, d, s1);
                    d = av[u].y - v1[u].y; s1 = fmaf(d, d, s1);
                    d = av[u].z - v1[u].z; s1 = fmaf(d, d, s1);
                    d = av[u].w - v1[u].w; s1 = fmaf(d, d, s1);
                    d = av[u].x - v2[u].x; s2 = fmaf(d, d, s2);
                    d = av[u].y - v2[u].y; s2 = fmaf(d, d, s2);
                    d = av[u].z - v2[u].z; s2 = fmaf(d, d, s2);
                    d = av[u].w - v2[u].w; s2 = fmaf(d, d, s2);
                }
            }
        } else {
            for (int j = lane; j < n4; j += 32) {
                float4 av = A[j];
                float4 v1 = T1[j];
                float4 v2 = T2[j];
                float d;
                d = av.x - v1.x; s1 = fmaf(d, d, s1);
                d = av.y - v1.y; s1 = fmaf(d, d, s1);
                d = av.z - v1.z; s1 = fmaf(d, d, s1);
                d = av.w - v1.w; s1 = fmaf(d, d, s1);
                d = av.x - v2.x; s2 = fmaf(d, d, s2);
                d = av.y - v2.y; s2 = fmaf(d, d, s2);
                d = av.z - v2.z; s2 = fmaf(d, d, s2);
                d = av.w - v2.w; s2 = fmaf(d, d, s2);
            }
        }

        s1 = warp_sum(s1);
        s2 = warp_sum(s2);

        if (lane == 0) {
            const float mu    = (float)136.72353790613718;
            const float sigma = (float)62.34640414043511;

            float li_raw = label[i];
            float la = label[a]; if (a < i) la = (la - mu) / sigma;  // normalized by earlier step
            float lb = label[b]; if (b < i) lb = (lb - mu) / sigma;

            float ld1 = fabsf(li_raw - la);
            float ld2 = fabsf(li_raw - lb);
            bool cond = (ld1 >= ld2);

            float dp = cond ? s2 : s1;    // anchor->near squared distance
            float dn = cond ? s1 : s2;    // anchor->far  squared distance
            float near_l = cond ? lb : la;
            float far_l  = cond ? la : lb;

            float li = (li_raw - mu) / sigma;
            float nl = (near_l - mu) / sigma;  // may be double-normalized — matches reference
            float fl = (far_l  - mu) / sigma;

            float alpha = (li - fl) * (li - fl) - (li - nl) * (li - nl);
            float l = dp - dn + 0.5f * alpha;
            loss = l > 0.f ? l : 0.f;
        }
    }

    if (lane == 0) wloss[wid] = loss;
    __syncthreads();

    if (threadIdx.x == 0) {
        float s = 0.f;
        #pragma unroll
        for (int w = 0; w < 8; w++) s += wloss[w];
        __stcg(&g_block[blockIdx.x], s);   // bypass L1, publish to L2
        __threadfence();
        unsigned int old = atomicAdd(&g_count, 1u);
        isLast = (old == (unsigned int)gridDim.x - 1u);
    }
    __syncthreads();

    if (isLast) {
        // All partials are L2-hot (just written via __stcg). Fixed order.
        const int nb = gridDim.x;
        float s = 0.f;
        for (int j = (int)threadIdx.x; j < nb; j += 256)
            s += __ldcg(&g_block[j]);

        __shared__ float sh[8];
        s = warp_sum(s);
        if (lane == 0) sh[wid] = s;
        __syncthreads();
        if (threadIdx.x == 0) {
            float t = 0.f;
            #pragma unroll
            for (int w = 0; w < 8; w++) t += sh[w];
            out[0] = t;
            g_count = 0;  // reset for next graph replay
        }
    }
}

extern "C" void kernel_launch(void* const* d_in, const int* in_sizes, int n_in,
                              void* d_out, int out_size) {
    const float* feats = (const float*)d_in[0];
    const float* label = (const float*)d_in[1];
    const int*   idx1  = (const int*)d_in[2];
    const int*   idx2  = (const int*)d_in[3];

    const int B = in_sizes[1];
    const int D = in_sizes[0] / B;
    const int nblocks = (B + 7) / 8;

    triplet_fused<<<nblocks, 256>>>(feats, label, idx1, idx2, (float*)d_out, B, D);
}

// round 7
// speedup vs baseline: 1.1048x; 1.1048x over previous
#include <cuda_runtime.h>

// Per-CTA partial sums + completion counter. 16384/8 = 2048 CTAs for this problem.
__device__ float g_block[65536];
__device__ unsigned int g_count = 0;

__device__ __forceinline__ float warp_sum(float v) {
    #pragma unroll
    for (int off = 16; off > 0; off >>= 1)
        v += __shfl_down_sync(0xFFFFFFFFu, v, off);
    return v;
}

// One warp per i, 8 warps per CTA. Each warp computes loss_i (post-relu);
// CTA sums its 8 losses into g_block[bid]; last CTA reduces all partials
// (fixed order -> deterministic). Completion signaled by an acq_rel atomic
// (NOT __threadfence: gpu-scope fence emits CCTL.IVALL = full L1D flush,
// which measurably slowed the cache-dependent main loop in R5).
__global__ void __launch_bounds__(256)
triplet_fused(const float* __restrict__ feats,
              const float* __restrict__ label,
              const int*   __restrict__ idx1,
              const int*   __restrict__ idx2,
              float* __restrict__ out,
              int B, int D) {
    const int lane = threadIdx.x & 31;
    const int wid  = threadIdx.x >> 5;
    const int i    = blockIdx.x * 8 + wid;

    __shared__ float wloss[8];
    __shared__ bool  isLast;
    float loss = 0.f;

    if (i < B) {
        // _fix_indices replication (all lanes; broadcast loads of same address)
        const int r1 = idx1[i];
        const int r2 = idx2[i];
        int a = (i + 1 + (r1 % (B - 1))) % B;
        int b = (i + 1 + (r2 % (B - 1))) % B;
        if (b == a) b = (i + 1 + ((r2 + 1) % (B - 1))) % B;

        const float4* __restrict__ A  = (const float4*)(feats + (size_t)i * D);
        const float4* __restrict__ T1 = (const float4*)(feats + (size_t)a * D);
        const float4* __restrict__ T2 = (const float4*)(feats + (size_t)b * D);

        const int n4 = D >> 2;   // 512 for D=2048
        float s1 = 0.f, s2 = 0.f;

        if ((n4 & 127) == 0) {
            // Chunks of 4 j-steps per warp: 12 front-batched float4 loads.
            // Anchor via __ldcs (evict-first): streamed once sequentially,
            // leaves L2 room for the random gather working set.
            const int nchunk = n4 >> 7;          // 4 for D=2048
            for (int c = 0; c < nchunk; ++c) {
                const int base = lane + c * 128;
                float4 av[4], v1[4], v2[4];
                #pragma unroll
                for (int u = 0; u < 4; ++u) av[u] = __ldcs(&A[base + u * 32]);
                #pragma unroll
                for (int u = 0; u < 4; ++u) v1[u] = T1[base + u * 32];
                #pragma unroll
                for (int u = 0; u < 4; ++u) v2[u] = T2[base + u * 32];
                #pragma unroll
                for (int u = 0; u < 4; ++u) {
                    float d;
                    d = av[u].x - v1[u].x; s1 = fmaf(d, d, s1);
                    d = av[u].y - v1[u].y; s1 = fmaf(d, d, s1);
                    d = av[u].z - v1[u].z; s1 = fmaf(d, d, s1);
                    d = av[u].w - v1[u].w; s1 = fmaf(d, d, s1);
                    d = av[u].x - v2[u].x; s2 = fmaf(d, d, s2);
                    d = av[u].y - v2[u].y; s2 = fmaf(d, d, s2);
                    d = av[u].z - v2[u].z; s2 = fmaf(d, d, s2);
                    d = av[u].w - v2[u].w; s2 = fmaf(d, d, s2);
                }
            }
        } else {
            for (int j = lane; j < n4; j += 32) {
                float4 av = A[j];
                float4 v1 = T1[j];
                float4 v2 = T2[j];
                float d;
                d = av.x - v1.x; s1 = fmaf(d, d, s1);
                d = av.y - v1.y; s1 = fmaf(d, d, s1);
                d = av.z - v1.z; s1 = fmaf(d, d, s1);
                d = av.w - v1.w; s1 = fmaf(d, d, s1);
                d = av.x - v2.x; s2 = fmaf(d, d, s2);
                d = av.y - v2.y; s2 = fmaf(d, d, s2);
                d = av.z - v2.z; s2 = fmaf(d, d, s2);
                d = av.w - v2.w; s2 = fmaf(d, d, s2);
            }
        }

        s1 = warp_sum(s1);
        s2 = warp_sum(s2);

        if (lane == 0) {
            const float mu    = (float)136.72353790613718;
            const float sigma = (float)62.34640414043511;

            float li_raw = label[i];
            float la = label[a]; if (a < i) la = (la - mu) / sigma;  // normalized by earlier step
            float lb = label[b]; if (b < i) lb = (lb - mu) / sigma;

            float ld1 = fabsf(li_raw - la);
            float ld2 = fabsf(li_raw - lb);
            bool cond = (ld1 >= ld2);

            float dp = cond ? s2 : s1;    // anchor->near squared distance
            float dn = cond ? s1 : s2;    // anchor->far  squared distance
            float near_l = cond ? lb : la;
            float far_l  = cond ? la : lb;

            float li = (li_raw - mu) / sigma;
            float nl = (near_l - mu) / sigma;  // may be double-normalized — matches reference
            float fl = (far_l  - mu) / sigma;

            float alpha = (li - fl) * (li - fl) - (li - nl) * (li - nl);
            float l = dp - dn + 0.5f * alpha;
            loss = l > 0.f ? l : 0.f;
        }
    }

    if (lane == 0) wloss[wid] = loss;
    __syncthreads();

    if (threadIdx.x == 0) {
        float s = 0.f;
        #pragma unroll
        for (int w = 0; w < 8; w++) s += wloss[w];
        __stcg(&g_block[blockIdx.x], s);   // bypass L1, publish to L2

        // acq_rel atomic: releases the __stcg above, acquires for the
        // __ldcg reads below. No CCTL.IVALL (unlike __threadfence).
        unsigned int old;
        asm volatile("atom.acq_rel.gpu.global.add.u32 %0, [%1], %2;"
                     : "=r"(old) : "l"(&g_count), "r"(1u) : "memory");
        isLast = (old == (unsigned int)gridDim.x - 1u);
    }
    __syncthreads();

    if (isLast) {
        // Partials are L2-hot (just written via __stcg). Fixed order.
        const int nb = gridDim.x;
        float s = 0.f;
        for (int j = (int)threadIdx.x; j < nb; j += 256)
            s += __ldcg(&g_block[j]);

        __shared__ float sh[8];
        s = warp_sum(s);
        if (lane == 0) sh[wid] = s;
        __syncthreads();
        if (threadIdx.x == 0) {
            float t = 0.f;
            #pragma unroll
            for (int w = 0; w < 8; w++) t += sh[w];
            out[0] = t;
            g_count = 0;  // reset for next graph replay
        }
    }
}

extern "C" void kernel_launch(void* const* d_in, const int* in_sizes, int n_in,
                              void* d_out, int out_size) {
    const float* feats = (const float*)d_in[0];
    const float* label = (const float*)d_in[1];
    const int*   idx1  = (const int*)d_in[2];
    const int*   idx2  = (const int*)d_in[3];

    const int B = in_sizes[1];
    const int D = in_sizes[0] / B;
    const int nblocks = (B + 7) / 8;

    triplet_fused<<<nblocks, 256>>>(feats, label, idx1, idx2, (float*)d_out, B, D);
}